// round 2
// baseline (speedup 1.0000x reference)
#include <cuda_runtime.h>
#include <cstdint>

// SimCLR NT-Xent loss, fused.
//   feats = normalize(concat(z1,z2))           (K0)
//   rowsum[i] = sum_{j != i, |i-j| != 4096} exp(cos(i,j)/T - 10)   (K1, symmetric tiles)
//   loss = mean(-cos(i,pos)/T + 10 + log(rowsum[i]))               (K2)
//
// Fixed-shift exp (logits in [-10,10]) removes the need for online max,
// which lets tile (I,J), I<=J, scatter into BOTH rowsum[i] and rowsum[j]
// (mask is symmetric), halving GEMM flops.

#define N2 8192
#define HALF 4096
#define D 128
#define NT 64                    // number of 128-row tiles
#define NPAIRS (NT*(NT+1)/2)     // 2080
#define BM 128
#define BK 32
#define INV_T 10.0f
#define SHIFT 10.0f

__device__ __align__(16) float g_feats[N2 * D];
__device__ float g_rowsum[N2];

// ---------------------------------------------------------------- K0
__global__ void k0_normalize(const float* __restrict__ z1,
                             const float* __restrict__ z2,
                             float* __restrict__ out) {
    int row = blockIdx.x;
    int t = threadIdx.x;              // 128 threads, one per feature
    const float* src = (row < HALF) ? (z1 + (size_t)row * D)
                                    : (z2 + (size_t)(row - HALF) * D);
    float v = src[t];
    float s = v * v;
    #pragma unroll
    for (int o = 16; o; o >>= 1) s += __shfl_xor_sync(0xffffffffu, s, o);
    __shared__ float ws[4];
    if ((t & 31) == 0) ws[t >> 5] = s;
    __syncthreads();
    float tot = ws[0] + ws[1] + ws[2] + ws[3];
    g_feats[row * D + t] = v * rsqrtf(fmaxf(tot, 1e-24f));
    if (t == 0) {
        g_rowsum[row] = 0.0f;
        if (row == 0) out[0] = 0.0f;
    }
}

// ---------------------------------------------------------------- K1
// One block per (I,J) 128x128 tile pair, I<=J. 256 threads, 8x8 per thread
// (8 rows x 4 packed f32x2 column-pairs). Packed fp32 FMA (fma.rn.f32x2)
// doubles fp32 throughput vs scalar FFMA (which is half-rate on Blackwell).
__global__ __launch_bounds__(256, 2) void k1_tiles() {
    __shared__ float As[BK][BM + 1];               // k-major, stride 129
    __shared__ __align__(16) float Bs[BK][BM + 2]; // k-major, stride 130 (even: f32x2 loads)
    __shared__ float colbuf[8][BM];

    // decode bid -> (I,J), I<=J (uniform across block)
    int k = blockIdx.x;
    int I = 0;
    while (k >= NT - I) { k -= NT - I; ++I; }
    int J = I + k;

    int tid = threadIdx.x;
    int tx = tid & 15;        // column group
    int ty = tid >> 4;        // row group

    const float* A = g_feats + (size_t)I * BM * D;
    const float* B = g_feats + (size_t)J * BM * D;

    unsigned long long acc[8][4];
    #pragma unroll
    for (int m = 0; m < 8; ++m)
        #pragma unroll
        for (int n = 0; n < 4; ++n) acc[m][n] = 0ull;

    for (int c = 0; c < D / BK; ++c) {
        __syncthreads();
        // stage A,B chunk [BM][BK] transposed to k-major shared
        #pragma unroll
        for (int t = 0; t < 4; ++t) {
            int p = t * 256 + tid;
            int r = p >> 3, q = p & 7;
            float4 va = *(const float4*)(A + r * D + c * BK + q * 4);
            As[q * 4 + 0][r] = va.x; As[q * 4 + 1][r] = va.y;
            As[q * 4 + 2][r] = va.z; As[q * 4 + 3][r] = va.w;
            float4 vb = *(const float4*)(B + r * D + c * BK + q * 4);
            Bs[q * 4 + 0][r] = vb.x; Bs[q * 4 + 1][r] = vb.y;
            Bs[q * 4 + 2][r] = vb.z; Bs[q * 4 + 3][r] = vb.w;
        }
        __syncthreads();
        #pragma unroll 8
        for (int kk = 0; kk < BK; ++kk) {
            unsigned long long bfrag[4];
            #pragma unroll
            for (int n = 0; n < 4; ++n)
                bfrag[n] = *(const unsigned long long*)&Bs[kk][2 * tx + 32 * n];
            #pragma unroll
            for (int m = 0; m < 8; ++m) {
                float av = As[kk][ty * 8 + m];
                unsigned long long ad;
                asm("mov.b64 %0, {%1, %1};" : "=l"(ad) : "f"(av));
                #pragma unroll
                for (int n = 0; n < 4; ++n)
                    asm("fma.rn.f32x2 %0, %1, %2, %0;"
                        : "+l"(acc[m][n]) : "l"(ad), "l"(bfrag[n]));
            }
        }
    }

    // epilogue: e = exp(s*10 - 10), masked; accumulate row/col partials
    bool diagT = (I == J);
    bool posT  = (J - I == 32);   // |i-j|==4096 only possible here
    float rsum[8], csum[8];
    #pragma unroll
    for (int m = 0; m < 8; ++m) rsum[m] = 0.0f;
    #pragma unroll
    for (int cI = 0; cI < 8; ++cI) csum[cI] = 0.0f;

    int gi0 = I * BM + ty * 8;
    int gj0 = J * BM + 2 * tx;
    #pragma unroll
    for (int m = 0; m < 8; ++m) {
        int gi = gi0 + m;
        #pragma unroll
        for (int n = 0; n < 4; ++n) {
            float lo, hi;
            asm("mov.b64 {%0, %1}, %2;" : "=f"(lo), "=f"(hi) : "l"(acc[m][n]));
            int gj = gj0 + 32 * n;
            float e0 = __expf(fmaf(lo, INV_T, -SHIFT));
            float e1 = __expf(fmaf(hi, INV_T, -SHIFT));
            if (diagT) { if (gi == gj) e0 = 0.0f; if (gi == gj + 1) e1 = 0.0f; }
            if (posT)  { if (gj - gi == HALF) e0 = 0.0f; if (gj + 1 - gi == HALF) e1 = 0.0f; }
            rsum[m] += e0 + e1;
            csum[2 * n] += e0;
            csum[2 * n + 1] += e1;
        }
    }

    // row sums: reduce over the 16 tx threads (xor within 16-lane halves)
    #pragma unroll
    for (int m = 0; m < 8; ++m) {
        float r = rsum[m];
        #pragma unroll
        for (int o = 1; o < 16; o <<= 1) r += __shfl_xor_sync(0xffffffffu, r, o);
        if (tx == 0) atomicAdd(&g_rowsum[gi0 + m], r);
    }

    // col sums: combine the 2 ty's in each warp via xor 16, park in shared,
    // then 128 threads fold 8 warps and scatter (skip for diagonal tiles).
    int w = tid >> 5;
    int lane = tid & 31;
    #pragma unroll
    for (int cI = 0; cI < 8; ++cI) {
        float cv = csum[cI] + __shfl_xor_sync(0xffffffffu, csum[cI], 16);
        if (lane < 16) colbuf[w][2 * tx + 32 * (cI >> 1) + (cI & 1)] = cv;
    }
    __syncthreads();
    if (!diagT && tid < BM) {
        float tot = 0.0f;
        #pragma unroll
        for (int ww = 0; ww < 8; ++ww) tot += colbuf[ww][tid];
        atomicAdd(&g_rowsum[J * BM + tid], tot);
    }
}

// ---------------------------------------------------------------- K2
// One warp per row: pos_sim dot + final loss, mean-reduced into out[0].
__global__ void k2_final(float* __restrict__ out) {
    int row = (blockIdx.x * blockDim.x + threadIdx.x) >> 5;
    int lane = threadIdx.x & 31;
    const float4* a = (const float4*)(g_feats + (size_t)row * D);
    int p = (row + HALF) & (N2 - 1);
    const float4* b = (const float4*)(g_feats + (size_t)p * D);
    float4 x = a[lane], y = b[lane];
    float dot = x.x * y.x + x.y * y.y + x.z * y.z + x.w * y.w;
    #pragma unroll
    for (int o = 16; o; o >>= 1) dot += __shfl_xor_sync(0xffffffffu, dot, o);

    __shared__ float bs[8];
    if (lane == 0) {
        float lossv = (-dot * INV_T + SHIFT + logf(g_rowsum[row])) * (1.0f / N2);
        bs[threadIdx.x >> 5] = lossv;
    }
    __syncthreads();
    if (threadIdx.x == 0) {
        float s = 0.0f;
        #pragma unroll
        for (int i = 0; i < 8; ++i) s += bs[i];
        atomicAdd(out, s);
    }
}

// ---------------------------------------------------------------- launch
extern "C" void kernel_launch(void* const* d_in, const int* in_sizes, int n_in,
                              void* d_out, int out_size) {
    const float* z1 = (const float*)d_in[0];
    const float* z2 = (const float*)d_in[1];
    float* out = (float*)d_out;

    k0_normalize<<<N2, 128>>>(z1, z2, out);
    k1_tiles<<<NPAIRS, 256>>>();
    k2_final<<<N2 / 8, 256>>>(out);
}

// round 6
// speedup vs baseline: 1.7685x; 1.7685x over previous
#include <cuda_runtime.h>
#include <cuda_bf16.h>
#include <cstdint>

// SimCLR NT-Xent loss — mma.sync (sm_100 plain target; tcgen05 unavailable).
// K0: normalize rows -> fp32 feats + bf16 hi/lo split (f = hi + lo).
// K1: persistent CTAs over symmetric 128x128 tile pairs (I<=J).
//     S = Ahi.Bhi^T + Alo.Bhi^T + Ahi.Blo^T  via ldmatrix + mma.sync m16n8k16 bf16,
//     fp32 accumulators in registers; epilogue exp(10 s - 10), mask, scatter
//     row (I side) + col (J side) sums with atomics. cp.async double-buffered B.
// K2: loss = mean(-10*pos + 10 + log(rowsum)), pos dot in fp32.

#define N2 8192
#define HALF 4096
#define D 128
#define NT 64
#define NPAIRS 2080
#define NSM 148
#define INV_T 10.0f
#define SHIFT 10.0f

__device__ __align__(16) float g_feats[N2 * D];
__device__ __align__(16) __nv_bfloat16 g_hi[N2 * D];
__device__ __align__(16) __nv_bfloat16 g_lo[N2 * D];
__device__ float g_rowsum[N2];

#define SW128(o) ((o) ^ (((o) >> 3) & 0x70))

// ---------------- SMEM layout ----------------
// tile = 128 rows x 128 bf16 = 32KB, stored as two 16KB atom-columns
// (cols 0-63 / 64-127), each [16 8-row blocks][8 rows x 128B], SW128 swizzled.
#define T_AH 0
#define T_AL 32768
#define T_B  65536            /* two bufs of 64KB: hi at +buf*65536, lo +32768 */
#define T_ROWP 196608         /* float rowpart[8][64] = 2048 B */
#define T_COLP 198656         /* float colpart[8][32] = 1024 B */
#define SMEM_TOTAL 199680

__device__ __forceinline__ uint32_t smem_u32(const void* p) {
    uint32_t a;
    asm("{ .reg .u64 t; cvta.to.shared.u64 t, %1; cvt.u32.u64 %0, t; }" : "=r"(a) : "l"(p));
    return a;
}

// swizzled byte offset of (row r, 16B-unit g) inside a 128x128 bf16 tile
__device__ __forceinline__ uint32_t tile_off(int r, int g) {
    uint32_t off = (uint32_t)(((r >> 3) + (g >> 3) * 16) * 1024 + (r & 7) * 128 + (g & 7) * 16);
    return SW128(off);
}

__device__ __forceinline__ void stage_async(const __nv_bfloat16* __restrict__ src,
                                            int rowbase, uint32_t dst, int tid) {
    const char* s = (const char*)(src + (size_t)rowbase * D);
    #pragma unroll
    for (int it = 0; it < 8; ++it) {
        int q = it * 256 + tid;           // 2048 16B chunks
        int r = q >> 4, g = q & 15;
        uint32_t d = dst + tile_off(r, g);
        asm volatile("cp.async.cg.shared.global [%0], [%1], 16;"
                     :: "r"(d), "l"(s + r * 256 + g * 16) : "memory");
    }
}

#define CP_COMMIT() asm volatile("cp.async.commit_group;" ::: "memory")
#define CP_WAIT0()  asm volatile("cp.async.wait_group 0;" ::: "memory")

#define LDSM_X4(R, A)                                                          \
    asm volatile("ldmatrix.sync.aligned.m8n8.x4.shared.b16 {%0,%1,%2,%3}, [%4];" \
        : "=r"((R)[0]), "=r"((R)[1]), "=r"((R)[2]), "=r"((R)[3]) : "r"(A))

__device__ __forceinline__ void mma16816(float* c, const uint32_t* a,
                                         uint32_t b0, uint32_t b1) {
    asm volatile("mma.sync.aligned.m16n8k16.row.col.f32.bf16.bf16.f32 "
        "{%0,%1,%2,%3}, {%4,%5,%6,%7}, {%8,%9}, {%0,%1,%2,%3};"
        : "+f"(c[0]), "+f"(c[1]), "+f"(c[2]), "+f"(c[3])
        : "r"(a[0]), "r"(a[1]), "r"(a[2]), "r"(a[3]), "r"(b0), "r"(b1));
}

// ---------------------------------------------------------------- K0
__global__ void k0_normalize(const float* __restrict__ z1,
                             const float* __restrict__ z2,
                             float* __restrict__ out) {
    int w = threadIdx.x >> 5, lane = threadIdx.x & 31;
    int row = blockIdx.x * 4 + w;
    const float* src = (row < HALF) ? (z1 + (size_t)row * D)
                                    : (z2 + (size_t)(row - HALF) * D);
    float4 f = ((const float4*)src)[lane];
    float ss = f.x * f.x + f.y * f.y + f.z * f.z + f.w * f.w;
    #pragma unroll
    for (int o = 16; o; o >>= 1) ss += __shfl_xor_sync(0xffffffffu, ss, o);
    float inv = rsqrtf(fmaxf(ss, 1e-24f));
    f.x *= inv; f.y *= inv; f.z *= inv; f.w *= inv;
    ((float4*)(g_feats + (size_t)row * D))[lane] = f;

    __nv_bfloat16 h[4], l[4];
    float vv[4] = {f.x, f.y, f.z, f.w};
    #pragma unroll
    for (int i = 0; i < 4; ++i) {
        h[i] = __float2bfloat16(vv[i]);
        l[i] = __float2bfloat16(vv[i] - __bfloat162float(h[i]));
    }
    uint32_t hp0 = (uint32_t)*(uint16_t*)&h[0] | ((uint32_t)*(uint16_t*)&h[1] << 16);
    uint32_t hp1 = (uint32_t)*(uint16_t*)&h[2] | ((uint32_t)*(uint16_t*)&h[3] << 16);
    uint32_t lp0 = (uint32_t)*(uint16_t*)&l[0] | ((uint32_t)*(uint16_t*)&l[1] << 16);
    uint32_t lp1 = (uint32_t)*(uint16_t*)&l[2] | ((uint32_t)*(uint16_t*)&l[3] << 16);
    ((uint2*)(g_hi + (size_t)row * D))[lane] = make_uint2(hp0, hp1);
    ((uint2*)(g_lo + (size_t)row * D))[lane] = make_uint2(lp0, lp1);
    if (lane == 0) g_rowsum[row] = 0.0f;
    if (blockIdx.x == 0 && threadIdx.x == 0) out[0] = 0.0f;
}

// ---------------------------------------------------------------- K1
__device__ __forceinline__ void decode_tile(int t, int& I, int& J) {
    int k = t, i = 0;
    while (k >= NT - i) { k -= NT - i; ++i; }
    I = i; J = i + k;
}

__global__ void __launch_bounds__(256, 1) k1_mma() {
    extern __shared__ char smem[];
    uint32_t sb = smem_u32(smem);
    float* rowpart = (float*)(smem + T_ROWP);   // [8][64]
    float* colpart = (float*)(smem + T_COLP);   // [8][32]
    int tid = threadIdx.x, lane = tid & 31, w = tid >> 5;
    int wy = w >> 2, wx = w & 3;               // warp tile: rows wy*64, cols wx*32

    int start = (int)((long long)blockIdx.x * NPAIRS / NSM);
    int end   = (int)((long long)(blockIdx.x + 1) * NPAIRS / NSM);
    if (start >= end) return;

    int I, J;
    decode_tile(start, I, J);
    int buf = 0;
    stage_async(g_hi, I * 128, sb + T_AH, tid);
    stage_async(g_lo, I * 128, sb + T_AL, tid);
    stage_async(g_hi, J * 128, sb + T_B, tid);
    stage_async(g_lo, J * 128, sb + T_B + 32768, tid);
    CP_COMMIT(); CP_WAIT0();
    __syncthreads();

    for (int t = start; t < end; ++t) {
        bool havenext = (t + 1 < end);
        int nI = I, nJ = J;
        if (havenext) decode_tile(t + 1, nI, nJ);
        bool pf = havenext && (nI == I);
        if (pf) {   // prefetch next B into other buffer, overlapped with compute
            stage_async(g_hi, nJ * 128, sb + T_B + (buf ^ 1) * 65536, tid);
            stage_async(g_lo, nJ * 128, sb + T_B + (buf ^ 1) * 65536 + 32768, tid);
            CP_COMMIT();
        }

        // ---------------- compute: 3 splits x 8 k16-steps ----------------
        float acc[4][4][4];
        #pragma unroll
        for (int mt = 0; mt < 4; ++mt)
            #pragma unroll
            for (int nt = 0; nt < 4; ++nt)
                #pragma unroll
                for (int r = 0; r < 4; ++r) acc[mt][nt][r] = 0.0f;

        int rA = lane & 15;
        int rB = ((lane >> 4) << 3) + (lane & 7);
        #pragma unroll
        for (int s = 0; s < 3; ++s) {
            uint32_t Ab = sb + (s == 1 ? T_AL : T_AH);
            uint32_t Bb = sb + T_B + buf * 65536 + (s == 2 ? 32768 : 0);
            #pragma unroll
            for (int k0 = 0; k0 < 8; ++k0) {
                int gA = k0 * 2 + (lane >> 4);
                int gB = k0 * 2 + ((lane >> 3) & 1);
                uint32_t a[4][4], b[2][4];
                #pragma unroll
                for (int mt = 0; mt < 4; ++mt)
                    LDSM_X4(a[mt], Ab + tile_off(wy * 64 + mt * 16 + rA, gA));
                #pragma unroll
                for (int np = 0; np < 2; ++np)
                    LDSM_X4(b[np], Bb + tile_off(wx * 32 + np * 16 + rB, gB));
                #pragma unroll
                for (int mt = 0; mt < 4; ++mt)
                    #pragma unroll
                    for (int nt = 0; nt < 4; ++nt)
                        mma16816(acc[mt][nt], a[mt],
                                 b[nt >> 1][(nt & 1) * 2], b[nt >> 1][(nt & 1) * 2 + 1]);
            }
        }

        // I-run ends next iteration: issue the A(+B) reload NOW so the L2
        // fetch overlaps the epilogue below (compute has finished reading A).
        bool reload = havenext && !pf;
        if (reload) {
            __syncthreads();   // all warps done with ldsm reads of A/B
            stage_async(g_hi, nI * 128, sb + T_AH, tid);
            stage_async(g_lo, nI * 128, sb + T_AL, tid);
            stage_async(g_hi, nJ * 128, sb + T_B + buf * 65536, tid);
            stage_async(g_lo, nJ * 128, sb + T_B + buf * 65536 + 32768, tid);
            CP_COMMIT();
        }

        // ---------------- epilogue ----------------
        // mask: both diag (I==J) and positive-pair (J-I==32) reduce to row_loc==col_loc
        bool maskT = (I == J) || (J - I == 32);
        float rs[4][2], cs[4][2];
        #pragma unroll
        for (int i = 0; i < 4; ++i) { rs[i][0] = rs[i][1] = cs[i][0] = cs[i][1] = 0.f; }
        int rl0 = wy * 64 + (lane >> 2);          // + mt*16 (+8)
        int cl0 = wx * 32 + (lane & 3) * 2;       // + nt*8 (+1)
        #pragma unroll
        for (int mt = 0; mt < 4; ++mt) {
            int R0 = rl0 + mt * 16, R1 = R0 + 8;
            #pragma unroll
            for (int nt = 0; nt < 4; ++nt) {
                int C0 = cl0 + nt * 8, C1 = C0 + 1;
                float* c = acc[mt][nt];
                float e0 = __expf(fmaf(c[0], INV_T, -SHIFT));
                float e1 = __expf(fmaf(c[1], INV_T, -SHIFT));
                float e2 = __expf(fmaf(c[2], INV_T, -SHIFT));
                float e3 = __expf(fmaf(c[3], INV_T, -SHIFT));
                if (maskT) {
                    if (R0 == C0) e0 = 0.f;
                    if (R0 == C1) e1 = 0.f;
                    if (R1 == C0) e2 = 0.f;
                    if (R1 == C1) e3 = 0.f;
                }
                rs[mt][0] += e0 + e1; rs[mt][1] += e2 + e3;
                cs[nt][0] += e0 + e2; cs[nt][1] += e1 + e3;
            }
        }
        // row partials: reduce across the 4 lanes of each row-quad
        #pragma unroll
        for (int mt = 0; mt < 4; ++mt) {
            #pragma unroll
            for (int h = 0; h < 2; ++h) {
                float v = rs[mt][h];
                v += __shfl_xor_sync(0xffffffffu, v, 1);
                v += __shfl_xor_sync(0xffffffffu, v, 2);
                if ((lane & 3) == 0)
                    rowpart[w * 64 + mt * 16 + (lane >> 2) + h * 8] = v;
            }
        }
        // col partials: reduce across the 8 lanes sharing a column set
        #pragma unroll
        for (int nt = 0; nt < 4; ++nt) {
            #pragma unroll
            for (int h = 0; h < 2; ++h) {
                float v = cs[nt][h];
                v += __shfl_xor_sync(0xffffffffu, v, 4);
                v += __shfl_xor_sync(0xffffffffu, v, 8);
                v += __shfl_xor_sync(0xffffffffu, v, 16);
                if (lane < 4)
                    colpart[w * 32 + nt * 8 + lane * 2 + h] = v;
            }
        }
        __syncthreads();
        if (tid < 128) {
            int i = tid;
            int h4 = (i >> 6) * 4, il = i & 63;
            float rtot = rowpart[(h4 + 0) * 64 + il] + rowpart[(h4 + 1) * 64 + il]
                       + rowpart[(h4 + 2) * 64 + il] + rowpart[(h4 + 3) * 64 + il];
            atomicAdd(&g_rowsum[I * 128 + i], rtot);
            int jx = i >> 5, jl = i & 31;
            float ctot = colpart[jx * 32 + jl] + colpart[(4 + jx) * 32 + jl];
            if (I != J) atomicAdd(&g_rowsum[J * 128 + i], ctot);
        }
        __syncthreads();

        // ---------------- advance ----------------
        if (havenext) {
            CP_WAIT0();
            __syncthreads();
            if (pf) buf ^= 1;
            I = nI; J = nJ;
        }
    }
}

// ---------------------------------------------------------------- K2
__global__ void k2_final(float* __restrict__ out) {
    int row = (blockIdx.x * blockDim.x + threadIdx.x) >> 5;
    int lane = threadIdx.x & 31;
    const float4* a = (const float4*)(g_feats + (size_t)row * D);
    int p = (row + HALF) & (N2 - 1);
    const float4* b = (const float4*)(g_feats + (size_t)p * D);
    float4 x = a[lane], y = b[lane];
    float dot = x.x * y.x + x.y * y.y + x.z * y.z + x.w * y.w;
    #pragma unroll
    for (int o = 16; o; o >>= 1) dot += __shfl_xor_sync(0xffffffffu, dot, o);

    __shared__ float bs[8];
    if (lane == 0) {
        float lossv = (-dot * INV_T + SHIFT + logf(g_rowsum[row])) * (1.0f / N2);
        bs[threadIdx.x >> 5] = lossv;
    }
    __syncthreads();
    if (threadIdx.x == 0) {
        float s = 0.0f;
        #pragma unroll
        for (int i = 0; i < 8; ++i) s += bs[i];
        atomicAdd(out, s);
    }
}

// ---------------------------------------------------------------- launch
extern "C" void kernel_launch(void* const* d_in, const int* in_sizes, int n_in,
                              void* d_out, int out_size) {
    const float* z1 = (const float*)d_in[0];
    const float* z2 = (const float*)d_in[1];
    float* out = (float*)d_out;

    cudaFuncSetAttribute(k1_mma, cudaFuncAttributeMaxDynamicSharedMemorySize, SMEM_TOTAL);

    k0_normalize<<<N2 / 4, 128>>>(z1, z2, out);
    k1_mma<<<NSM, 256, SMEM_TOTAL>>>();
    k2_final<<<N2 / 8, 256>>>(out);
}

// round 8
// speedup vs baseline: 4.2029x; 2.3765x over previous
#include <cuda_runtime.h>
#include <cuda_bf16.h>
#include <cstdint>

// SimCLR NT-Xent loss — single-bf16 mma.sync (sm_100 plain target).
// K0: normalize rows -> fp32 feats (for exact pos term) + bf16 feats (GEMM).
// K1: persistent CTAs (2/SM) over symmetric 128x128 tile pairs (I<=J).
//     S = A.B^T via ldmatrix + mma.sync m16n8k16 bf16 (fp32 acc in regs);
//     epilogue e = exp2(14.427 s - 14.427) = exp(10 s - 10), mask, scatter
//     row (I) + col (J) sums with atomics. bf16 error only perturbs the
//     logsumexp denominator (softmax-weighted average -> cancels to ~1e-5).
// K2: loss = mean(-10*pos + 10 + log(rowsum)), pos dot exact in fp32.

#define N2 8192
#define HALF 4096
#define D 128
#define NT 64
#define NPAIRS 2080
#define NSM 148
#define NBLK (2 * NSM)
#define INV_T 10.0f
#define SHIFT 10.0f
#define C_EX2 14.426950408889634f   /* 10 * log2(e) */

__device__ __align__(16) float g_feats[N2 * D];
__device__ __align__(16) __nv_bfloat16 g_bf[N2 * D];
__device__ float g_rowsum[N2];

#define SW128(o) ((o) ^ (((o) >> 3) & 0x70))

// ---------------- SMEM layout ----------------
// tile = 128 rows x 128 bf16 = 32KB, stored as two 16KB atom-columns
// (cols 0-63 / 64-127), each [16 8-row blocks][8 rows x 128B], SW128 swizzled.
#define T_A 0
#define T_B 32768             /* two bufs of 32KB at +buf*32768 */
#define T_ROWP 98304          /* float rowpart[8][64] = 2048 B */
#define T_COLP 100352         /* float colpart[8][32] = 1024 B */
#define SMEM_TOTAL 101376     /* x2 CTAs = 198KB/SM */

__device__ __forceinline__ uint32_t smem_u32(const void* p) {
    uint32_t a;
    asm("{ .reg .u64 t; cvta.to.shared.u64 t, %1; cvt.u32.u64 %0, t; }" : "=r"(a) : "l"(p));
    return a;
}

// swizzled byte offset of (row r, 16B-unit g) inside a 128x128 bf16 tile
__device__ __forceinline__ uint32_t tile_off(int r, int g) {
    uint32_t off = (uint32_t)(((r >> 3) + (g >> 3) * 16) * 1024 + (r & 7) * 128 + (g & 7) * 16);
    return SW128(off);
}

__device__ __forceinline__ void stage_async(const __nv_bfloat16* __restrict__ src,
                                            int rowbase, uint32_t dst, int tid) {
    const char* s = (const char*)(src + (size_t)rowbase * D);
    #pragma unroll
    for (int it = 0; it < 8; ++it) {
        int q = it * 256 + tid;           // 2048 16B chunks
        int r = q >> 4, g = q & 15;
        uint32_t d = dst + tile_off(r, g);
        asm volatile("cp.async.cg.shared.global [%0], [%1], 16;"
                     :: "r"(d), "l"(s + r * 256 + g * 16) : "memory");
    }
}

#define CP_COMMIT() asm volatile("cp.async.commit_group;" ::: "memory")
#define CP_WAIT0()  asm volatile("cp.async.wait_group 0;" ::: "memory")

#define LDSM_X4(R, A)                                                          \
    asm volatile("ldmatrix.sync.aligned.m8n8.x4.shared.b16 {%0,%1,%2,%3}, [%4];" \
        : "=r"((R)[0]), "=r"((R)[1]), "=r"((R)[2]), "=r"((R)[3]) : "r"(A))

__device__ __forceinline__ void mma16816(float* c, const uint32_t* a,
                                         uint32_t b0, uint32_t b1) {
    asm volatile("mma.sync.aligned.m16n8k16.row.col.f32.bf16.bf16.f32 "
        "{%0,%1,%2,%3}, {%4,%5,%6,%7}, {%8,%9}, {%0,%1,%2,%3};"
        : "+f"(c[0]), "+f"(c[1]), "+f"(c[2]), "+f"(c[3])
        : "r"(a[0]), "r"(a[1]), "r"(a[2]), "r"(a[3]), "r"(b0), "r"(b1));
}

__device__ __forceinline__ float ex2f(float x) {
    float r;
    asm("ex2.approx.ftz.f32 %0, %1;" : "=f"(r) : "f"(x));
    return r;
}

// ---------------------------------------------------------------- K0
__global__ void k0_normalize(const float* __restrict__ z1,
                             const float* __restrict__ z2,
                             float* __restrict__ out) {
    int w = threadIdx.x >> 5, lane = threadIdx.x & 31;
    int row = blockIdx.x * 8 + w;
    const float* src = (row < HALF) ? (z1 + (size_t)row * D)
                                    : (z2 + (size_t)(row - HALF) * D);
    float4 f = ((const float4*)src)[lane];
    float ss = f.x * f.x + f.y * f.y + f.z * f.z + f.w * f.w;
    #pragma unroll
    for (int o = 16; o; o >>= 1) ss += __shfl_xor_sync(0xffffffffu, ss, o);
    float inv = rsqrtf(fmaxf(ss, 1e-24f));
    f.x *= inv; f.y *= inv; f.z *= inv; f.w *= inv;
    ((float4*)(g_feats + (size_t)row * D))[lane] = f;

    __nv_bfloat162 b0 = __floats2bfloat162_rn(f.x, f.y);
    __nv_bfloat162 b1 = __floats2bfloat162_rn(f.z, f.w);
    ((uint2*)(g_bf + (size_t)row * D))[lane] =
        make_uint2(*(uint32_t*)&b0, *(uint32_t*)&b1);
    if (lane == 0) g_rowsum[row] = 0.0f;
    if (blockIdx.x == 0 && threadIdx.x == 0) out[0] = 0.0f;
}

// ---------------------------------------------------------------- K1
__device__ __forceinline__ void decode_tile(int t, int& I, int& J) {
    int k = t, i = 0;
    while (k >= NT - i) { k -= NT - i; ++i; }
    I = i; J = i + k;
}

__global__ void __launch_bounds__(256, 2) k1_mma() {
    extern __shared__ char smem[];
    uint32_t sb = smem_u32(smem);
    float* rowpart = (float*)(smem + T_ROWP);   // [8][64]
    float* colpart = (float*)(smem + T_COLP);   // [8][32]
    int tid = threadIdx.x, lane = tid & 31, w = tid >> 5;
    int wy = w >> 2, wx = w & 3;               // warp tile: rows wy*64, cols wx*32

    int start = (int)((long long)blockIdx.x * NPAIRS / NBLK);
    int end   = (int)((long long)(blockIdx.x + 1) * NPAIRS / NBLK);
    if (start >= end) return;

    int I, J;
    decode_tile(start, I, J);
    int buf = 0;
    stage_async(g_bf, I * 128, sb + T_A, tid);
    stage_async(g_bf, J * 128, sb + T_B, tid);
    CP_COMMIT(); CP_WAIT0();
    __syncthreads();

    for (int t = start; t < end; ++t) {
        bool havenext = (t + 1 < end);
        int nI = I, nJ = J;
        if (havenext) decode_tile(t + 1, nI, nJ);
        bool pf = havenext && (nI == I);
        if (pf) {   // prefetch next B into other buffer, overlapped with compute
            stage_async(g_bf, nJ * 128, sb + T_B + (buf ^ 1) * 32768, tid);
            CP_COMMIT();
        }

        // ---------------- compute: 8 k16-steps ----------------
        float acc[4][4][4];
        #pragma unroll
        for (int mt = 0; mt < 4; ++mt)
            #pragma unroll
            for (int nt = 0; nt < 4; ++nt)
                #pragma unroll
                for (int r = 0; r < 4; ++r) acc[mt][nt][r] = 0.0f;

        int rA = lane & 15;
        int rB = ((lane >> 4) << 3) + (lane & 7);
        uint32_t Ab = sb + T_A;
        uint32_t Bb = sb + T_B + buf * 32768;
        #pragma unroll
        for (int k0 = 0; k0 < 8; ++k0) {
            int gA = k0 * 2 + (lane >> 4);
            int gB = k0 * 2 + ((lane >> 3) & 1);
            uint32_t a[4][4], b[2][4];
            #pragma unroll
            for (int mt = 0; mt < 4; ++mt)
                LDSM_X4(a[mt], Ab + tile_off(wy * 64 + mt * 16 + rA, gA));
            #pragma unroll
            for (int np = 0; np < 2; ++np)
                LDSM_X4(b[np], Bb + tile_off(wx * 32 + np * 16 + rB, gB));
            #pragma unroll
            for (int mt = 0; mt < 4; ++mt)
                #pragma unroll
                for (int nt = 0; nt < 4; ++nt)
                    mma16816(acc[mt][nt], a[mt],
                             b[nt >> 1][(nt & 1) * 2], b[nt >> 1][(nt & 1) * 2 + 1]);
        }

        // I-run ends next iteration: issue the A(+B) reload NOW so the L2
        // fetch overlaps the epilogue below (compute has finished reading A).
        bool reload = havenext && !pf;
        if (reload) {
            __syncthreads();   // all warps done with ldsm reads of A/B
            stage_async(g_bf, nI * 128, sb + T_A, tid);
            stage_async(g_bf, nJ * 128, sb + T_B + buf * 32768, tid);
            CP_COMMIT();
        }

        // ---------------- epilogue ----------------
        // mask: both diag (I==J) and positive-pair (J-I==32) reduce to row_loc==col_loc
        bool maskT = (I == J) || (J - I == 32);
        float rs[4][2], cs[4][2];
        #pragma unroll
        for (int i = 0; i < 4; ++i) { rs[i][0] = rs[i][1] = cs[i][0] = cs[i][1] = 0.f; }
        int rl0 = wy * 64 + (lane >> 2);          // + mt*16 (+8)
        int cl0 = wx * 32 + (lane & 3) * 2;       // + nt*8 (+1)
        #pragma unroll
        for (int mt = 0; mt < 4; ++mt) {
            int R0 = rl0 + mt * 16, R1 = R0 + 8;
            #pragma unroll
            for (int nt = 0; nt < 4; ++nt) {
                int C0 = cl0 + nt * 8, C1 = C0 + 1;
                float* c = acc[mt][nt];
                float e0 = ex2f(fmaf(c[0], C_EX2, -C_EX2));
                float e1 = ex2f(fmaf(c[1], C_EX2, -C_EX2));
                float e2 = ex2f(fmaf(c[2], C_EX2, -C_EX2));
                float e3 = ex2f(fmaf(c[3], C_EX2, -C_EX2));
                if (maskT) {
                    if (R0 == C0) e0 = 0.f;
                    if (R0 == C1) e1 = 0.f;
                    if (R1 == C0) e2 = 0.f;
                    if (R1 == C1) e3 = 0.f;
                }
                rs[mt][0] += e0 + e1; rs[mt][1] += e2 + e3;
                cs[nt][0] += e0 + e2; cs[nt][1] += e1 + e3;
            }
        }
        // row partials: reduce across the 4 lanes of each row-quad
        #pragma unroll
        for (int mt = 0; mt < 4; ++mt) {
            #pragma unroll
            for (int h = 0; h < 2; ++h) {
                float v = rs[mt][h];
                v += __shfl_xor_sync(0xffffffffu, v, 1);
                v += __shfl_xor_sync(0xffffffffu, v, 2);
                if ((lane & 3) == 0)
                    rowpart[w * 64 + mt * 16 + (lane >> 2) + h * 8] = v;
            }
        }
        // col partials: reduce across the 8 lanes sharing a column set
        #pragma unroll
        for (int nt = 0; nt < 4; ++nt) {
            #pragma unroll
            for (int h = 0; h < 2; ++h) {
                float v = cs[nt][h];
                v += __shfl_xor_sync(0xffffffffu, v, 4);
                v += __shfl_xor_sync(0xffffffffu, v, 8);
                v += __shfl_xor_sync(0xffffffffu, v, 16);
                if (lane < 4)
                    colpart[w * 32 + nt * 8 + lane * 2 + h] = v;
            }
        }
        __syncthreads();
        if (tid < 128) {
            int i = tid;
            int h4 = (i >> 6) * 4, il = i & 63;
            float rtot = rowpart[(h4 + 0) * 64 + il] + rowpart[(h4 + 1) * 64 + il]
                       + rowpart[(h4 + 2) * 64 + il] + rowpart[(h4 + 3) * 64 + il];
            atomicAdd(&g_rowsum[I * 128 + i], rtot);
            int jx = i >> 5, jl = i & 31;
            float ctot = colpart[jx * 32 + jl] + colpart[(4 + jx) * 32 + jl];
            if (I != J) atomicAdd(&g_rowsum[J * 128 + i], ctot);
        }
        __syncthreads();

        // ---------------- advance ----------------
        if (havenext) {
            CP_WAIT0();
            __syncthreads();
            if (pf) buf ^= 1;
            I = nI; J = nJ;
        }
    }
}

// ---------------------------------------------------------------- K2
__global__ void k2_final(float* __restrict__ out) {
    int row = (blockIdx.x * blockDim.x + threadIdx.x) >> 5;
    int lane = threadIdx.x & 31;
    const float4* a = (const float4*)(g_feats + (size_t)row * D);
    int p = (row + HALF) & (N2 - 1);
    const float4* b = (const float4*)(g_feats + (size_t)p * D);
    float4 x = a[lane], y = b[lane];
    float dot = x.x * y.x + x.y * y.y + x.z * y.z + x.w * y.w;
    #pragma unroll
    for (int o = 16; o; o >>= 1) dot += __shfl_xor_sync(0xffffffffu, dot, o);

    __shared__ float bs[8];
    if (lane == 0) {
        float lossv = (-dot * INV_T + SHIFT + logf(g_rowsum[row])) * (1.0f / N2);
        bs[threadIdx.x >> 5] = lossv;
    }
    __syncthreads();
    if (threadIdx.x == 0) {
        float s = 0.0f;
        #pragma unroll
        for (int i = 0; i < 8; ++i) s += bs[i];
        atomicAdd(out, s);
    }
}

// ---------------------------------------------------------------- launch
extern "C" void kernel_launch(void* const* d_in, const int* in_sizes, int n_in,
                              void* d_out, int out_size) {
    const float* z1 = (const float*)d_in[0];
    const float* z2 = (const float*)d_in[1];
    float* out = (float*)d_out;

    cudaFuncSetAttribute(k1_mma, cudaFuncAttributeMaxDynamicSharedMemorySize, SMEM_TOTAL);

    k0_normalize<<<N2 / 8, 256>>>(z1, z2, out);
    k1_mma<<<NBLK, 256, SMEM_TOTAL>>>();
    k2_final<<<N2 / 8, 256>>>(out);
}